// round 5
// baseline (speedup 1.0000x reference)
#include <cuda_runtime.h>

#define IN_DIM   128
#define OUT_DIM  128
#define BATCH    1024
#define TB       8      // batch rows per block
#define NTHREADS 512

// output offsets (floats): y_out, preacts, postacts, postspline
#define OFF_YOUT  0
#define OFF_PRE   (BATCH * OUT_DIM)                    // 131072
#define OFF_POST  (OFF_PRE + BATCH * OUT_DIM * IN_DIM) // 16908288
#define OFF_SPL   (OFF_POST + BATCH * OUT_DIM * IN_DIM)// 33685504

__global__ __launch_bounds__(NTHREADS, 1)
void kan_kernel(const float* __restrict__ x,
                const float* __restrict__ gridp,
                const float* __restrict__ coef,
                const float* __restrict__ scale_base,
                const float* __restrict__ scale_sp,
                const float* __restrict__ maskp,
                float* __restrict__ out)
{
    __shared__ float bas[8][TB * IN_DIM];   // basis[c][bb*128+i]
    __shared__ float sil[TB * IN_DIM];
    __shared__ float xs[TB * IN_DIM];

    const int tid = threadIdx.x;
    const int b0  = blockIdx.x * TB;

    // ---- extended grid (all rows identical; use row 0, faithful to reference) ----
    float g[6];
#pragma unroll
    for (int m = 0; m < 6; m++) g[m] = gridp[m];
    const float h = (g[5] - g[0]) * 0.2f;   // (g_last - g_first) / NUM
    float e[12];
#pragma unroll
    for (int m = 0; m < 12; m++) {
        if (m < 3)      e[m] = g[0] - (float)(3 - m) * h;
        else if (m < 9) e[m] = g[m - 3];
        else            e[m] = g[5] + (float)(m - 8) * h;
    }

    // ---- phase 1: basis + silu + x for TB*128 = 1024 (b,i) pairs ----
#pragma unroll
    for (int rep = 0; rep < (TB * IN_DIM) / NTHREADS; rep++) {
        const int idx = tid + rep * NTHREADS;          // bb*128 + i
        const float xv = x[b0 * IN_DIM + idx];

        float B[11];
#pragma unroll
        for (int m = 0; m < 11; m++)
            B[m] = (xv >= e[m] && xv < e[m + 1]) ? 1.0f : 0.0f;
        // p = 1
#pragma unroll
        for (int m = 0; m < 10; m++)
            B[m] = __fdividef(xv - e[m],     e[m + 1] - e[m])     * B[m]
                 + __fdividef(e[m + 2] - xv, e[m + 2] - e[m + 1]) * B[m + 1];
        // p = 2
#pragma unroll
        for (int m = 0; m < 9; m++)
            B[m] = __fdividef(xv - e[m],     e[m + 2] - e[m])     * B[m]
                 + __fdividef(e[m + 3] - xv, e[m + 3] - e[m + 1]) * B[m + 1];
        // p = 3
#pragma unroll
        for (int m = 0; m < 8; m++)
            B[m] = __fdividef(xv - e[m],     e[m + 3] - e[m])     * B[m]
                 + __fdividef(e[m + 4] - xv, e[m + 4] - e[m + 1]) * B[m + 1];

#pragma unroll
        for (int c = 0; c < 8; c++) bas[c][idx] = B[c];
        sil[idx] = xv * __fdividef(1.0f, 1.0f + __expf(-xv));
        xs[idx]  = xv;
    }
    __syncthreads();

    // ---- phase 2: main loop over (jj, bb) ----
    const int lane = tid & 31;
    const int warp = tid >> 5;
    const int ib   = lane * 4;

    float* __restrict__ outY   = out + OFF_YOUT;
    float* __restrict__ outPre = out + OFF_PRE;
    float* __restrict__ outPost= out + OFF_POST;
    float* __restrict__ outSpl = out + OFF_SPL;

#pragma unroll 1
    for (int jj = 0; jj < OUT_DIM / 16; jj++) {
        const int j = jj * 16 + warp;
        const int s0 = j * IN_DIM + ib;      // first of 4 s-values

        float4 ca[4], cb[4];
#pragma unroll
        for (int q = 0; q < 4; q++) {
            ca[q] = ((const float4*)coef)[(s0 + q) * 2];
            cb[q] = ((const float4*)coef)[(s0 + q) * 2 + 1];
        }
        const float4 m4  = *(const float4*)&maskp[s0];
        const float4 sb4 = *(const float4*)&scale_base[s0];
        const float4 ss4 = *(const float4*)&scale_sp[s0];

#pragma unroll 1
        for (int bb = 0; bb < TB; bb++) {
            const int o = bb * IN_DIM + ib;
            float4 b4[8];
#pragma unroll
            for (int c = 0; c < 8; c++) b4[c] = *(const float4*)&bas[c][o];

            float4 sp;
#define DOT8(CA, CB, comp) (CA.x * b4[0].comp + CA.y * b4[1].comp + \
                            CA.z * b4[2].comp + CA.w * b4[3].comp + \
                            CB.x * b4[4].comp + CB.y * b4[5].comp + \
                            CB.z * b4[6].comp + CB.w * b4[7].comp)
            sp.x = DOT8(ca[0], cb[0], x);
            sp.y = DOT8(ca[1], cb[1], y);
            sp.z = DOT8(ca[2], cb[2], z);
            sp.w = DOT8(ca[3], cb[3], w);
#undef DOT8

            const float4 sl  = *(const float4*)&sil[o];
            const float4 xv4 = *(const float4*)&xs[o];

            float4 y;
            y.x = m4.x * (sb4.x * sl.x + ss4.x * sp.x);
            y.y = m4.y * (sb4.y * sl.y + ss4.y * sp.y);
            y.z = m4.z * (sb4.z * sl.z + ss4.z * sp.z);
            y.w = m4.w * (sb4.w * sl.w + ss4.w * sp.w);

            const int base = ((b0 + bb) * OUT_DIM + j) * IN_DIM + ib;
            *(float4*)&outPre[base]  = xv4;
            *(float4*)&outPost[base] = y;
            *(float4*)&outSpl[base]  = sp;

            // y_out reduction across the 32 lanes (128 i-values)
            float ysum = y.x + y.y + y.z + y.w;
#pragma unroll
            for (int off = 16; off > 0; off >>= 1)
                ysum += __shfl_xor_sync(0xFFFFFFFFu, ysum, off);
            if (lane == 0)
                outY[(b0 + bb) * OUT_DIM + j] = ysum;
        }
    }
}

extern "C" void kernel_launch(void* const* d_in, const int* in_sizes, int n_in,
                              void* d_out, int out_size)
{
    const float* x          = (const float*)d_in[0];
    const float* grid       = (const float*)d_in[1];
    const float* coef       = (const float*)d_in[2];
    const float* scale_base = (const float*)d_in[3];
    const float* scale_sp   = (const float*)d_in[4];
    const float* mask       = (const float*)d_in[5];
    float* out = (float*)d_out;

    kan_kernel<<<BATCH / TB, NTHREADS>>>(x, grid, coef, scale_base, scale_sp, mask, out);
}

// round 8
// speedup vs baseline: 1.0786x; 1.0786x over previous
#include <cuda_runtime.h>

#define IN_DIM   128
#define OUT_DIM  128
#define BATCH    1024
#define TB       8           // batch rows per block
#define JSPLIT   4           // j-range split across blocks
#define JBLK     (OUT_DIM / JSPLIT)   // 32 j per block
#define NTHREADS 512

// output offsets (floats): y_out, preacts, postacts, postspline
#define OFF_YOUT  0
#define OFF_PRE   (BATCH * OUT_DIM)                    // 131072
#define OFF_POST  (OFF_PRE + BATCH * OUT_DIM * IN_DIM) // 16908288
#define OFF_SPL   (OFF_POST + BATCH * OUT_DIM * IN_DIM)// 33685504

__global__ __launch_bounds__(NTHREADS, 1)
void kan_kernel(const float* __restrict__ x,
                const float* __restrict__ gridp,
                const float* __restrict__ coef,
                const float* __restrict__ scale_base,
                const float* __restrict__ scale_sp,
                const float* __restrict__ maskp,
                float* __restrict__ out)
{
    __shared__ float bas[8][TB * IN_DIM];   // basis[c][bb*128+i]
    __shared__ float sil[TB * IN_DIM];
    __shared__ float xs[TB * IN_DIM];

    const int tid = threadIdx.x;
    const int bg  = blockIdx.x >> 2;              // batch group
    const int jb  = blockIdx.x & (JSPLIT - 1);    // j-slice
    const int b0  = bg * TB;

    // ---- extended grid (rows identical; row 0, faithful to reference) ----
    float g[6];
#pragma unroll
    for (int m = 0; m < 6; m++) g[m] = gridp[m];
    const float h = (g[5] - g[0]) * 0.2f;
    float e[12];
#pragma unroll
    for (int m = 0; m < 12; m++) {
        if (m < 3)      e[m] = g[0] - (float)(3 - m) * h;
        else if (m < 9) e[m] = g[m - 3];
        else            e[m] = g[5] + (float)(m - 8) * h;
    }

    // ---- phase 1: basis + silu + x for TB*128 = 1024 (b,i) pairs ----
#pragma unroll
    for (int rep = 0; rep < (TB * IN_DIM) / NTHREADS; rep++) {
        const int idx = tid + rep * NTHREADS;
        const float xv = x[b0 * IN_DIM + idx];

        float B[11];
#pragma unroll
        for (int m = 0; m < 11; m++)
            B[m] = (xv >= e[m] && xv < e[m + 1]) ? 1.0f : 0.0f;
#pragma unroll
        for (int m = 0; m < 10; m++)
            B[m] = __fdividef(xv - e[m],     e[m + 1] - e[m])     * B[m]
                 + __fdividef(e[m + 2] - xv, e[m + 2] - e[m + 1]) * B[m + 1];
#pragma unroll
        for (int m = 0; m < 9; m++)
            B[m] = __fdividef(xv - e[m],     e[m + 2] - e[m])     * B[m]
                 + __fdividef(e[m + 3] - xv, e[m + 3] - e[m + 1]) * B[m + 1];
#pragma unroll
        for (int m = 0; m < 8; m++)
            B[m] = __fdividef(xv - e[m],     e[m + 3] - e[m])     * B[m]
                 + __fdividef(e[m + 4] - xv, e[m + 4] - e[m + 1]) * B[m + 1];

#pragma unroll
        for (int c = 0; c < 8; c++) bas[c][idx] = B[c];
        sil[idx] = xv * __fdividef(1.0f, 1.0f + __expf(-xv));
        xs[idx]  = xv;
    }
    __syncthreads();

    // ---- phase 2: each warp owns 2 consecutive j; coef register-resident ----
    const int lane = tid & 31;
    const int warp = tid >> 5;
    const int ib   = lane * 4;
    const int j0   = jb * JBLK + warp * 2;        // this warp: j0, j0+1

    const int sA = j0 * IN_DIM + ib;
    const int sB = sA + IN_DIM;

    // coef[q][c] for 4 i-values (q) x 8 basis (c), both j
    float cf0[4][8], cf1[4][8];
#pragma unroll
    for (int q = 0; q < 4; q++) {
        *(float4*)&cf0[q][0] = ((const float4*)coef)[(sA + q) * 2];
        *(float4*)&cf0[q][4] = ((const float4*)coef)[(sA + q) * 2 + 1];
        *(float4*)&cf1[q][0] = ((const float4*)coef)[(sB + q) * 2];
        *(float4*)&cf1[q][4] = ((const float4*)coef)[(sB + q) * 2 + 1];
    }

    // premultiplied scales: msb = mask*scale_base, mss = mask*scale_sp
    float4 msbA, mssA, msbB, mssB;
    {
        const float4 mA  = *(const float4*)&maskp[sA];
        const float4 sbA = *(const float4*)&scale_base[sA];
        const float4 ssA = *(const float4*)&scale_sp[sA];
        msbA = make_float4(mA.x*sbA.x, mA.y*sbA.y, mA.z*sbA.z, mA.w*sbA.w);
        mssA = make_float4(mA.x*ssA.x, mA.y*ssA.y, mA.z*ssA.z, mA.w*ssA.w);
        const float4 mB  = *(const float4*)&maskp[sB];
        const float4 sbB = *(const float4*)&scale_base[sB];
        const float4 ssB = *(const float4*)&scale_sp[sB];
        msbB = make_float4(mB.x*sbB.x, mB.y*sbB.y, mB.z*sbB.z, mB.w*sbB.w);
        mssB = make_float4(mB.x*ssB.x, mB.y*ssB.y, mB.z*ssB.z, mB.w*ssB.w);
    }

    float* __restrict__ outY   = out + OFF_YOUT;
    float* __restrict__ outPre = out + OFF_PRE;
    float* __restrict__ outPost= out + OFF_POST;
    float* __restrict__ outSpl = out + OFF_SPL;

#pragma unroll 1
    for (int bb = 0; bb < TB; bb++) {
        const int o = bb * IN_DIM + ib;

        float4 sp0 = make_float4(0.f, 0.f, 0.f, 0.f);
        float4 sp1 = make_float4(0.f, 0.f, 0.f, 0.f);
#pragma unroll
        for (int c = 0; c < 8; c++) {
            const float4 b = *(const float4*)&bas[c][o];   // B[c] for 4 i
            sp0.x += cf0[0][c] * b.x;  sp0.y += cf0[1][c] * b.y;
            sp0.z += cf0[2][c] * b.z;  sp0.w += cf0[3][c] * b.w;
            sp1.x += cf1[0][c] * b.x;  sp1.y += cf1[1][c] * b.y;
            sp1.z += cf1[2][c] * b.z;  sp1.w += cf1[3][c] * b.w;
        }

        const float4 sl = *(const float4*)&sil[o];
        const float4 xv = *(const float4*)&xs[o];

        float4 y0, y1;
        y0.x = msbA.x*sl.x + mssA.x*sp0.x;  y0.y = msbA.y*sl.y + mssA.y*sp0.y;
        y0.z = msbA.z*sl.z + mssA.z*sp0.z;  y0.w = msbA.w*sl.w + mssA.w*sp0.w;
        y1.x = msbB.x*sl.x + mssB.x*sp1.x;  y1.y = msbB.y*sl.y + mssB.y*sp1.y;
        y1.z = msbB.z*sl.z + mssB.z*sp1.z;  y1.w = msbB.w*sl.w + mssB.w*sp1.w;

        const int base0 = ((b0 + bb) * OUT_DIM + j0) * IN_DIM + ib;
        const int base1 = base0 + IN_DIM;

        __stcs((float4*)&outPre[base0],  xv);
        __stcs((float4*)&outPre[base1],  xv);
        __stcs((float4*)&outPost[base0], y0);
        __stcs((float4*)&outPost[base1], y1);
        __stcs((float4*)&outSpl[base0],  sp0);
        __stcs((float4*)&outSpl[base1],  sp1);

        // y_out reductions across 32 lanes (covers all 128 i)
        float ys0 = y0.x + y0.y + y0.z + y0.w;
        float ys1 = y1.x + y1.y + y1.z + y1.w;
#pragma unroll
        for (int off = 16; off > 0; off >>= 1) {
            ys0 += __shfl_xor_sync(0xFFFFFFFFu, ys0, off);
            ys1 += __shfl_xor_sync(0xFFFFFFFFu, ys1, off);
        }
        if (lane == 0) {
            outY[(b0 + bb) * OUT_DIM + j0]     = ys0;
            outY[(b0 + bb) * OUT_DIM + j0 + 1] = ys1;
        }
    }
}

extern "C" void kernel_launch(void* const* d_in, const int* in_sizes, int n_in,
                              void* d_out, int out_size)
{
    const float* x          = (const float*)d_in[0];
    const float* grid       = (const float*)d_in[1];
    const float* coef       = (const float*)d_in[2];
    const float* scale_base = (const float*)d_in[3];
    const float* scale_sp   = (const float*)d_in[4];
    const float* mask       = (const float*)d_in[5];
    float* out = (float*)d_out;

    kan_kernel<<<(BATCH / TB) * JSPLIT, NTHREADS>>>(x, grid, coef, scale_base, scale_sp, mask, out);
}

// round 13
// speedup vs baseline: 1.1144x; 1.0332x over previous
#include <cuda_runtime.h>

#define IN_DIM   128
#define OUT_DIM  128
#define BATCH    1024
#define TB       8           // batch rows per block
#define JSPLIT   4           // j-range split across blocks
#define JBLK     (OUT_DIM / JSPLIT)   // 32 j per block
#define NTHREADS 512
#define NWARP    (NTHREADS / 32)      // 16

// output offsets (floats): y_out, preacts, postacts, postspline
#define OFF_YOUT  0
#define OFF_PRE   (BATCH * OUT_DIM)                    // 131072
#define OFF_POST  (OFF_PRE + BATCH * OUT_DIM * IN_DIM) // 16908288
#define OFF_SPL   (OFF_POST + BATCH * OUT_DIM * IN_DIM)// 33685504

__global__ __launch_bounds__(NTHREADS, 1)
void kan_kernel(const float* __restrict__ x,
                const float* __restrict__ gridp,
                const float* __restrict__ coef,
                const float* __restrict__ scale_base,
                const float* __restrict__ scale_sp,
                const float* __restrict__ maskp,
                float* __restrict__ out)
{
    __shared__ float bas[8][TB * IN_DIM];   // basis[c][bb*128+i]
    __shared__ float sil[TB * IN_DIM];
    __shared__ float xs[TB * IN_DIM];
    __shared__ float ypart[TB][NWARP][2][32];   // [bb][warp][j2][lane] 32KB

    const int tid = threadIdx.x;
    const int bg  = blockIdx.x >> 2;              // batch group
    const int jb  = blockIdx.x & (JSPLIT - 1);    // j-slice
    const int b0  = bg * TB;

    // ---- extended grid (rows identical; row 0, faithful to reference) ----
    float g[6];
#pragma unroll
    for (int m = 0; m < 6; m++) g[m] = gridp[m];
    const float h = (g[5] - g[0]) * 0.2f;
    float e[12];
#pragma unroll
    for (int m = 0; m < 12; m++) {
        if (m < 3)      e[m] = g[0] - (float)(3 - m) * h;
        else if (m < 9) e[m] = g[m - 3];
        else            e[m] = g[5] + (float)(m - 8) * h;
    }

    // ---- phase 1: basis + silu + x for TB*128 = 1024 (b,i) pairs ----
#pragma unroll
    for (int rep = 0; rep < (TB * IN_DIM) / NTHREADS; rep++) {
        const int idx = tid + rep * NTHREADS;
        const float xv = x[b0 * IN_DIM + idx];

        float B[11];
#pragma unroll
        for (int m = 0; m < 11; m++)
            B[m] = (xv >= e[m] && xv < e[m + 1]) ? 1.0f : 0.0f;
#pragma unroll
        for (int m = 0; m < 10; m++)
            B[m] = __fdividef(xv - e[m],     e[m + 1] - e[m])     * B[m]
                 + __fdividef(e[m + 2] - xv, e[m + 2] - e[m + 1]) * B[m + 1];
#pragma unroll
        for (int m = 0; m < 9; m++)
            B[m] = __fdividef(xv - e[m],     e[m + 2] - e[m])     * B[m]
                 + __fdividef(e[m + 3] - xv, e[m + 3] - e[m + 1]) * B[m + 1];
#pragma unroll
        for (int m = 0; m < 8; m++)
            B[m] = __fdividef(xv - e[m],     e[m + 3] - e[m])     * B[m]
                 + __fdividef(e[m + 4] - xv, e[m + 4] - e[m + 1]) * B[m + 1];

#pragma unroll
        for (int c = 0; c < 8; c++) bas[c][idx] = B[c];
        sil[idx] = xv * __fdividef(1.0f, 1.0f + __expf(-xv));
        xs[idx]  = xv;
    }
    __syncthreads();

    // ---- phase 2: each warp owns 2 consecutive j; coef register-resident ----
    const int lane = tid & 31;
    const int warp = tid >> 5;
    const int ib   = lane * 4;
    const int j0   = jb * JBLK + warp * 2;        // this warp: j0, j0+1

    const int sA = j0 * IN_DIM + ib;
    const int sB = sA + IN_DIM;

    // coef[q][c] for 4 i-values (q) x 8 basis (c), both j
    float cf0[4][8], cf1[4][8];
#pragma unroll
    for (int q = 0; q < 4; q++) {
        *(float4*)&cf0[q][0] = ((const float4*)coef)[(sA + q) * 2];
        *(float4*)&cf0[q][4] = ((const float4*)coef)[(sA + q) * 2 + 1];
        *(float4*)&cf1[q][0] = ((const float4*)coef)[(sB + q) * 2];
        *(float4*)&cf1[q][4] = ((const float4*)coef)[(sB + q) * 2 + 1];
    }

    // premultiplied scales: msb = mask*scale_base, mss = mask*scale_sp
    float4 msbA, mssA, msbB, mssB;
    {
        const float4 mA  = *(const float4*)&maskp[sA];
        const float4 sbA = *(const float4*)&scale_base[sA];
        const float4 ssA = *(const float4*)&scale_sp[sA];
        msbA = make_float4(mA.x*sbA.x, mA.y*sbA.y, mA.z*sbA.z, mA.w*sbA.w);
        mssA = make_float4(mA.x*ssA.x, mA.y*ssA.y, mA.z*ssA.z, mA.w*ssA.w);
        const float4 mB  = *(const float4*)&maskp[sB];
        const float4 sbB = *(const float4*)&scale_base[sB];
        const float4 ssB = *(const float4*)&scale_sp[sB];
        msbB = make_float4(mB.x*sbB.x, mB.y*sbB.y, mB.z*sbB.z, mB.w*sbB.w);
        mssB = make_float4(mB.x*ssB.x, mB.y*ssB.y, mB.z*ssB.z, mB.w*ssB.w);
    }

    float* __restrict__ outY   = out + OFF_YOUT;
    float* __restrict__ outPre = out + OFF_PRE;
    float* __restrict__ outPost= out + OFF_POST;
    float* __restrict__ outSpl = out + OFF_SPL;

#pragma unroll 1
    for (int bb = 0; bb < TB; bb++) {
        const int o = bb * IN_DIM + ib;

        float4 sp0 = make_float4(0.f, 0.f, 0.f, 0.f);
        float4 sp1 = make_float4(0.f, 0.f, 0.f, 0.f);
#pragma unroll
        for (int c = 0; c < 8; c++) {
            const float4 b = *(const float4*)&bas[c][o];   // B[c] for 4 i
            sp0.x += cf0[0][c] * b.x;  sp0.y += cf0[1][c] * b.y;
            sp0.z += cf0[2][c] * b.z;  sp0.w += cf0[3][c] * b.w;
            sp1.x += cf1[0][c] * b.x;  sp1.y += cf1[1][c] * b.y;
            sp1.z += cf1[2][c] * b.z;  sp1.w += cf1[3][c] * b.w;
        }

        const float4 sl = *(const float4*)&sil[o];
        const float4 xv = *(const float4*)&xs[o];

        float4 y0, y1;
        y0.x = msbA.x*sl.x + mssA.x*sp0.x;  y0.y = msbA.y*sl.y + mssA.y*sp0.y;
        y0.z = msbA.z*sl.z + mssA.z*sp0.z;  y0.w = msbA.w*sl.w + mssA.w*sp0.w;
        y1.x = msbB.x*sl.x + mssB.x*sp1.x;  y1.y = msbB.y*sl.y + mssB.y*sp1.y;
        y1.z = msbB.z*sl.z + mssB.z*sp1.z;  y1.w = msbB.w*sl.w + mssB.w*sp1.w;

        const int base0 = ((b0 + bb) * OUT_DIM + j0) * IN_DIM + ib;
        const int base1 = base0 + IN_DIM;

        __stcs((float4*)&outPre[base0],  xv);
        __stcs((float4*)&outPre[base1],  xv);
        __stcs((float4*)&outPost[base0], y0);
        __stcs((float4*)&outPost[base1], y1);
        __stcs((float4*)&outSpl[base0],  sp0);
        __stcs((float4*)&outSpl[base1],  sp1);

        // stage lane partials; reduction deferred past the loop (STS = issue-only)
        ypart[bb][warp][0][lane] = (y0.x + y0.y) + (y0.z + y0.w);
        ypart[bb][warp][1][lane] = (y1.x + y1.y) + (y1.z + y1.w);
    }

    // ---- phase 3: batched y_out reduction, conflict-free rotated reads ----
    __syncthreads();
    if (tid < TB * NWARP * 2) {                   // 256 sums of 32
        const int bb = tid >> 5;
        const int wp = (tid >> 1) & (NWARP - 1);
        const int j2 = tid & 1;
        const float* p = &ypart[bb][wp][j2][0];

        float s0 = 0.f, s1 = 0.f, s2 = 0.f, s3 = 0.f;
#pragma unroll
        for (int k = 0; k < 32; k += 4) {
            s0 += p[(k + 0 + tid) & 31];
            s1 += p[(k + 1 + tid) & 31];
            s2 += p[(k + 2 + tid) & 31];
            s3 += p[(k + 3 + tid) & 31];
        }
        outY[(b0 + bb) * OUT_DIM + (jb * JBLK + wp * 2 + j2)] = (s0 + s1) + (s2 + s3);
    }
}

extern "C" void kernel_launch(void* const* d_in, const int* in_sizes, int n_in,
                              void* d_out, int out_size)
{
    const float* x          = (const float*)d_in[0];
    const float* grid       = (const float*)d_in[1];
    const float* coef       = (const float*)d_in[2];
    const float* scale_base = (const float*)d_in[3];
    const float* scale_sp   = (const float*)d_in[4];
    const float* mask       = (const float*)d_in[5];
    float* out = (float*)d_out;

    kan_kernel<<<(BATCH / TB) * JSPLIT, NTHREADS>>>(x, grid, coef, scale_base, scale_sp, mask, out);
}